// round 3
// baseline (speedup 1.0000x reference)
#include <cuda_runtime.h>
#include <cuda_bf16.h>
#include <math.h>

// Problem constants
#define NG      64          // num graphs
#define NN      512         // nodes per graph
#define GN      32768       // NG*NN
#define D_IN    128
#define E       256
#define NL      4
#define DFF     2048
#define NE_EDGE 524288
#define KSEL    128
#define NH      8
#define HD      32

#define OFF_SAMP (NE_EDGE)
#define OFF_PF   (NE_EDGE + NG * KSEL)

// ---------------- scratch (static device globals; no cudaMalloc allowed) ---
__device__ float g_h[(size_t)GN * E];       // 32 MB  hidden state
__device__ float g_qkv[(size_t)GN * 3 * E]; // 96 MB
__device__ float g_attn[(size_t)GN * E];    // 32 MB  attn output / ff2 output
__device__ float g_ff[(size_t)GN * DFF];    // 256 MB out-proj result then ff1 act
__device__ float g_probs[GN];
__device__ float g_pf[GN];

// ---------------- GEMM: C[M,N] = A[M,K] @ B[N,K]^T + bias, optional relu ---
// BM=BN=64, BK=16, 256 threads, 4x4 micro-tile per thread. All dims are
// exact multiples (M=32768; N in {256,768,2048}; K in {128,256,2048}).
__global__ void gemm_tn(const float* __restrict__ A, const float* __restrict__ B,
                        const float* __restrict__ bias, float* __restrict__ C,
                        int M, int N, int K, int relu)
{
    __shared__ float As[16][64];
    __shared__ float Bs[16][64];

    const int tid = threadIdx.x;
    const int tx = tid & 15;          // 0..15  (n direction)
    const int ty = tid >> 4;          // 0..15  (m direction)
    const int m0 = blockIdx.y * 64;
    const int n0 = blockIdx.x * 64;

    const float* Ab = A + (size_t)m0 * K;
    const float* Bb = B + (size_t)n0 * K;

    const int lrow  = tid >> 2;       // 0..63
    const int lcol4 = (tid & 3) * 4;  // 0,4,8,12

    float acc[4][4];
#pragma unroll
    for (int i = 0; i < 4; i++)
#pragma unroll
        for (int j = 0; j < 4; j++) acc[i][j] = 0.f;

    for (int k0 = 0; k0 < K; k0 += 16) {
        float4 av = *(const float4*)(Ab + (size_t)lrow * K + k0 + lcol4);
        float4 bv = *(const float4*)(Bb + (size_t)lrow * K + k0 + lcol4);
        As[lcol4 + 0][lrow] = av.x; As[lcol4 + 1][lrow] = av.y;
        As[lcol4 + 2][lrow] = av.z; As[lcol4 + 3][lrow] = av.w;
        Bs[lcol4 + 0][lrow] = bv.x; Bs[lcol4 + 1][lrow] = bv.y;
        Bs[lcol4 + 2][lrow] = bv.z; Bs[lcol4 + 3][lrow] = bv.w;
        __syncthreads();
#pragma unroll
        for (int k = 0; k < 16; k++) {
            float4 a = *(const float4*)&As[k][ty * 4];
            float4 b = *(const float4*)&Bs[k][tx * 4];
            float ar[4] = {a.x, a.y, a.z, a.w};
            float br[4] = {b.x, b.y, b.z, b.w};
#pragma unroll
            for (int i = 0; i < 4; i++)
#pragma unroll
                for (int j = 0; j < 4; j++)
                    acc[i][j] = fmaf(ar[i], br[j], acc[i][j]);
        }
        __syncthreads();
    }

#pragma unroll
    for (int i = 0; i < 4; i++) {
        int m = m0 + ty * 4 + i;
#pragma unroll
        for (int j = 0; j < 4; j++) {
            int n = n0 + tx * 4 + j;
            float c = acc[i][j] + bias[n];
            if (relu) c = fmaxf(c, 0.f);
            C[(size_t)m * N + n] = c;
        }
    }
}

// ---------------- flash-style attention (fp32) -----------------------------
// grid (NG*NH, NN/128), block 128. Each thread owns one query row (hd=32),
// streams K/V tiles of 64 rows through smem, online softmax in registers.
__global__ void attn_kernel(const float* __restrict__ qkv, float* __restrict__ out)
{
    __shared__ float Ks[64][32];
    __shared__ float Vs[64][32];

    const int g  = blockIdx.x >> 3;
    const int h  = blockIdx.x & 7;
    const int tid = threadIdx.x;
    const int qi = blockIdx.y * 128 + tid;       // 0..511
    const int hc = h * HD;
    const float* base = qkv + (size_t)g * NN * (3 * E);

    float q[HD];
#pragma unroll
    for (int d = 0; d < HD; d++) q[d] = base[(size_t)qi * (3 * E) + hc + d];

    float acc[HD];
#pragma unroll
    for (int d = 0; d < HD; d++) acc[d] = 0.f;
    float mval = -1e30f, l = 0.f;
    const float scale = 0.17677669529663687f;    // 1/sqrt(32)

#pragma unroll 1
    for (int kt = 0; kt < NN; kt += 64) {
        const int row  = tid >> 1;
        const int half = (tid & 1) * 16;
        const float* kp = base + (size_t)(kt + row) * (3 * E) + E + hc + half;
        const float* vp = base + (size_t)(kt + row) * (3 * E) + 2 * E + hc + half;
#pragma unroll
        for (int c = 0; c < 16; c += 4) {
            *(float4*)&Ks[row][half + c] = *(const float4*)(kp + c);
            *(float4*)&Vs[row][half + c] = *(const float4*)(vp + c);
        }
        __syncthreads();

#pragma unroll 1
        for (int jc = 0; jc < 64; jc += 16) {
            float s[16];
            float cmax = -1e30f;
#pragma unroll
            for (int j = 0; j < 16; j++) {
                float sv = 0.f;
#pragma unroll
                for (int d = 0; d < HD; d++) sv = fmaf(q[d], Ks[jc + j][d], sv);
                sv *= scale;
                s[j] = sv;
                cmax = fmaxf(cmax, sv);
            }
            float mnew = fmaxf(mval, cmax);
            float corr = __expf(mval - mnew);
            l *= corr;
#pragma unroll
            for (int d = 0; d < HD; d++) acc[d] *= corr;
#pragma unroll
            for (int j = 0; j < 16; j++) {
                float p = __expf(s[j] - mnew);
                l += p;
#pragma unroll
                for (int d = 0; d < HD; d++)
                    acc[d] = fmaf(p, Vs[jc + j][d], acc[d]);
            }
            mval = mnew;
        }
        __syncthreads();
    }

    float inv = 1.f / l;
    float* op = out + (size_t)(g * NN + qi) * E + hc;
#pragma unroll
    for (int d = 0; d < HD; d++) op[d] = acc[d] * inv;
}

// ---------------- fused residual + LayerNorm (two-pass, fp32) --------------
// one 256-thread block per row; h = LN(h + add) * w + b
__global__ void ln_kernel(float* __restrict__ h, const float* __restrict__ add,
                          const float* __restrict__ w, const float* __restrict__ b)
{
    __shared__ float red[256];
    const int r = blockIdx.x;
    const int t = threadIdx.x;
    const size_t off = (size_t)r * E + t;
    float x = h[off] + add[off];

    red[t] = x;
    __syncthreads();
#pragma unroll
    for (int s = 128; s > 0; s >>= 1) {
        if (t < s) red[t] += red[t + s];
        __syncthreads();
    }
    float mu = red[0] * (1.f / E);
    __syncthreads();

    float d = x - mu;
    red[t] = d * d;
    __syncthreads();
#pragma unroll
    for (int s = 128; s > 0; s >>= 1) {
        if (t < s) red[t] += red[t + s];
        __syncthreads();
    }
    float var = red[0] * (1.f / E);
    float y = d * rsqrtf(var + 1e-5f) * w[t] + b[t];
    h[off] = y;
}

// ---------------- score + sigmoid (warp per row) ---------------------------
__global__ void score_kernel(const float* __restrict__ h, const float* __restrict__ sw,
                             const float* __restrict__ sb, float* __restrict__ probs)
{
    const int warp = (blockIdx.x * blockDim.x + threadIdx.x) >> 5;
    const int lane = threadIdx.x & 31;
    if (warp >= GN) return;
    const float* hp = h + (size_t)warp * E;
    float s = 0.f;
#pragma unroll
    for (int k = 0; k < 8; k++) s = fmaf(hp[lane + k * 32], sw[lane + k * 32], s);
#pragma unroll
    for (int o = 16; o; o >>= 1) s += __shfl_xor_sync(0xffffffff, s, o);
    if (lane == 0) {
        s += sb[0];
        probs[warp] = 1.f / (1.f + expf(-s));
    }
}

// ---------------- per-graph top-k (k=128 of n=512) -------------------------
// Bitonic sort 512 (value desc, index asc tie-break = jax top_k), then sort
// the 128 winning indices ascending, emit sampled_nodes + probs_f.
__global__ void topk_kernel(const float* __restrict__ probs,
                            float* __restrict__ out, float* __restrict__ pf_buf)
{
    __shared__ unsigned long long keys[NN];
    __shared__ int sidx[KSEL];
    __shared__ int flags[NN];

    const int g = blockIdx.x;
    const int t = threadIdx.x;
    const float p = probs[g * NN + t];

    // probs > 0 always -> positive-float bit pattern preserves ordering
    unsigned int fb = __float_as_uint(p);
    keys[t] = ((unsigned long long)fb << 32) | (unsigned)(NN - 1 - t);
    __syncthreads();

    // bitonic sort, descending
    for (int k = 2; k <= NN; k <<= 1) {
        for (int j = k >> 1; j > 0; j >>= 1) {
            int ixj = t ^ j;
            if (ixj > t) {
                unsigned long long a = keys[t], b = keys[ixj];
                bool up = ((t & k) == 0);
                if (up ? (a < b) : (a > b)) { keys[t] = b; keys[ixj] = a; }
            }
            __syncthreads();
        }
    }

    if (t < KSEL) sidx[t] = NN - 1 - (int)(unsigned)(keys[t] & 0xFFFFFFFFu);
    __syncthreads();

    // sort selected indices ascending (128 elems; all threads keep syncing)
    for (int k = 2; k <= KSEL; k <<= 1) {
        for (int j = k >> 1; j > 0; j >>= 1) {
            int ixj = t ^ j;
            if (t < KSEL && ixj > t && ixj < KSEL) {
                int a = sidx[t], b = sidx[ixj];
                bool up = ((t & k) == 0);
                if (up ? (a > b) : (a < b)) { sidx[t] = b; sidx[ixj] = a; }
            }
            __syncthreads();
        }
    }

    flags[t] = 0;
    __syncthreads();
    if (t < KSEL) flags[sidx[t]] = 1;
    __syncthreads();

    if (t < KSEL)
        out[OFF_SAMP + g * KSEL + t] = (float)(g * NN + sidx[t]);

    // straight-through: indexes = (mask - p) + p ; probs_f = p * indexes
    float mask = (float)flags[t];
    float ind  = (mask - p) + p;
    float pf   = p * ind;
    pf_buf[g * NN + t] = pf;
    out[OFF_PF + g * NN + t] = pf;
}

// ---------------- edge weights ---------------------------------------------
__global__ void ew_kernel(const int* __restrict__ ei, const float* __restrict__ w,
                          const float* __restrict__ pf, float* __restrict__ out)
{
    int e = blockIdx.x * blockDim.x + threadIdx.x;
    if (e < NE_EDGE) {
        int s = ei[e];
        int d = ei[NE_EDGE + e];
        out[e] = w[e] * pf[s] * pf[d];
    }
}

// ---------------------------------------------------------------------------
extern "C" void kernel_launch(void* const* d_in, const int* in_sizes, int n_in,
                              void* d_out, int out_size)
{
    const float* x      = (const float*)d_in[0];
    const int*   ei     = (const int*)  d_in[1];
    const float* ew     = (const float*)d_in[2];
    const float* emb_w  = (const float*)d_in[3];
    const float* emb_b  = (const float*)d_in[4];
    const float* qkv_w  = (const float*)d_in[5];
    const float* qkv_b  = (const float*)d_in[6];
    const float* out_w  = (const float*)d_in[7];
    const float* out_b  = (const float*)d_in[8];
    const float* ln1_w  = (const float*)d_in[9];
    const float* ln1_b  = (const float*)d_in[10];
    const float* ln2_w  = (const float*)d_in[11];
    const float* ln2_b  = (const float*)d_in[12];
    const float* ff1_w  = (const float*)d_in[13];
    const float* ff1_b  = (const float*)d_in[14];
    const float* ff2_w  = (const float*)d_in[15];
    const float* ff2_b  = (const float*)d_in[16];
    const float* sc_w   = (const float*)d_in[17];
    const float* sc_b   = (const float*)d_in[18];
    float* out = (float*)d_out;

    float *h, *qkvb, *attn, *ff, *probs, *pf;
    cudaGetSymbolAddress((void**)&h,     g_h);
    cudaGetSymbolAddress((void**)&qkvb,  g_qkv);
    cudaGetSymbolAddress((void**)&attn,  g_attn);
    cudaGetSymbolAddress((void**)&ff,    g_ff);
    cudaGetSymbolAddress((void**)&probs, g_probs);
    cudaGetSymbolAddress((void**)&pf,    g_pf);

    // embedding: [GN,128] @ [256,128]^T -> h [GN,256]
    gemm_tn<<<dim3(E / 64, GN / 64), 256>>>(x, emb_w, emb_b, h, GN, E, D_IN, 0);

    for (int l = 0; l < NL; l++) {
        const float* qw = qkv_w + (size_t)l * 3 * E * E;
        const float* qb = qkv_b + (size_t)l * 3 * E;
        const float* ow = out_w + (size_t)l * E * E;
        const float* ob = out_b + (size_t)l * E;
        const float* f1w = ff1_w + (size_t)l * DFF * E;
        const float* f1b = ff1_b + (size_t)l * DFF;
        const float* f2w = ff2_w + (size_t)l * E * DFF;
        const float* f2b = ff2_b + (size_t)l * E;

        // qkv projection -> g_qkv [GN, 768]
        gemm_tn<<<dim3(3 * E / 64, GN / 64), 256>>>(h, qw, qb, qkvb, GN, 3 * E, E, 0);
        // attention -> g_attn [GN, 256]
        attn_kernel<<<dim3(NG * NH, NN / 128), 128>>>(qkvb, attn);
        // output projection -> g_ff (first GN*E floats)
        gemm_tn<<<dim3(E / 64, GN / 64), 256>>>(attn, ow, ob, ff, GN, E, E, 0);
        // h = LN1(h + proj)
        ln_kernel<<<GN, E>>>(h, ff, ln1_w + (size_t)l * E, ln1_b + (size_t)l * E);
        // ff1 + relu -> g_ff [GN, 2048]
        gemm_tn<<<dim3(DFF / 64, GN / 64), 256>>>(h, f1w, f1b, ff, GN, DFF, E, 1);
        // ff2 -> g_attn [GN, 256]
        gemm_tn<<<dim3(E / 64, GN / 64), 256>>>(ff, f2w, f2b, attn, GN, E, DFF, 0);
        // h = LN2(h + ff)
        ln_kernel<<<GN, E>>>(h, attn, ln2_w + (size_t)l * E, ln2_b + (size_t)l * E);
    }

    // score + sigmoid
    score_kernel<<<(GN * 32 + 255) / 256, 256>>>(h, sc_w, sc_b, probs);
    // per-graph top-k, probs_f, sampled_nodes
    topk_kernel<<<NG, NN>>>(probs, out, pf);
    // edge weights
    ew_kernel<<<(NE_EDGE + 255) / 256, 256>>>(ei, ew, pf, out);
}

// round 7
// speedup vs baseline: 2.5678x; 2.5678x over previous
#include <cuda_runtime.h>
#include <cuda_bf16.h>
#include <cstdint>
#include <math.h>

// Problem constants
#define NG      64          // num graphs
#define NN      512         // nodes per graph
#define GN      32768       // NG*NN
#define D_IN    128
#define E       256
#define NL      4
#define DFF     2048
#define NE_EDGE 524288
#define KSEL    128
#define NH      8
#define HD      32

#define OFF_SAMP (NE_EDGE)
#define OFF_PF   (NE_EDGE + NG * KSEL)

// ---------------- scratch (static device globals; no cudaMalloc allowed) ---
__device__ float g_h[(size_t)GN * E];       // 32 MB  hidden state
__device__ float g_qkv[(size_t)GN * 3 * E]; // 96 MB
__device__ float g_attn[(size_t)GN * E];    // 32 MB  attn output / ff2 output
__device__ float g_ff[(size_t)GN * DFF];    // 256 MB out-proj result then ff1 act
__device__ float g_probs[GN];
__device__ float g_pf[GN];

// ---------------- tf32 helpers ---------------------------------------------
__device__ __forceinline__ float tf32_rna(float x) {
    uint32_t r;
    asm("cvt.rna.tf32.f32 %0, %1;" : "=r"(r) : "f"(x));
    return __uint_as_float(r);
}

// mma.sync m16n8k8 tf32 (baseline sm_80+ PTX — works on plain sm_103 target)
__device__ __forceinline__ void mma_tf32(float* d, const uint32_t* a, const uint32_t* b) {
    asm volatile(
        "mma.sync.aligned.m16n8k8.row.col.f32.tf32.tf32.f32 "
        "{%0,%1,%2,%3}, {%4,%5,%6,%7}, {%8,%9}, {%0,%1,%2,%3};"
        : "+f"(d[0]), "+f"(d[1]), "+f"(d[2]), "+f"(d[3])
        : "r"(a[0]), "r"(a[1]), "r"(a[2]), "r"(a[3]), "r"(b[0]), "r"(b[1]));
}

// ---------------- tf32x3 tensor-core GEMM (mma.sync) -----------------------
// C[M,N] = A[M,K] @ B[N,K]^T + bias, optional relu.
// Block tile 128x64, BK=32, 256 threads = 8 warps (4x2), warp tile 32x32.
// A/B split to hi/lo tf32 in smem; 3 mma per tile-pair => ~fp32 accuracy.
#define BM   128
#define BN   64
#define BK   32
#define LDS_PAD 36                       // floats per smem row (32 + 4 pad)
#define SM_A_HI 0
#define SM_A_LO (BM * LDS_PAD)           // 4608
#define SM_B_HI (2 * BM * LDS_PAD)       // 9216
#define SM_B_LO (2 * BM * LDS_PAD + BN * LDS_PAD)
#define GEMM_SMEM ((2 * BM * LDS_PAD + 2 * BN * LDS_PAD) * 4)   // 55296 B

__global__ void __launch_bounds__(256, 2)
gemm_mma(const float* __restrict__ A, const float* __restrict__ B,
         const float* __restrict__ bias, float* __restrict__ C,
         int K, int N, int relu)
{
    extern __shared__ float sm[];
    float* As_hi = sm + SM_A_HI;
    float* As_lo = sm + SM_A_LO;
    float* Bs_hi = sm + SM_B_HI;
    float* Bs_lo = sm + SM_B_LO;

    const int tid  = threadIdx.x;
    const int warp = tid >> 5;
    const int lane = tid & 31;
    const int wm   = warp >> 1;          // 0..3  (m direction, 32 rows each)
    const int wn   = warp & 1;           // 0..1  (n direction, 32 cols each)
    const int gid  = lane >> 2;          // 0..7
    const int qid  = lane & 3;           // 0..3
    const int m0   = blockIdx.y * BM;
    const int n0   = blockIdx.x * BN;

    float acc[2][4][4];
#pragma unroll
    for (int i = 0; i < 2; i++)
#pragma unroll
        for (int j = 0; j < 4; j++)
#pragma unroll
            for (int t = 0; t < 4; t++) acc[i][j][t] = 0.f;

    for (int k0 = 0; k0 < K; k0 += BK) {
        // ---- global loads into regs ----
        float4 av[4], bv[2];
#pragma unroll
        for (int i = 0; i < 4; i++) {
            int idx = tid + 256 * i;             // 0..1023
            int r = idx >> 3, c4 = idx & 7;
            av[i] = *(const float4*)(A + (size_t)(m0 + r) * K + k0 + c4 * 4);
        }
#pragma unroll
        for (int i = 0; i < 2; i++) {
            int idx = tid + 256 * i;             // 0..511
            int r = idx >> 3, c4 = idx & 7;
            bv[i] = *(const float4*)(B + (size_t)(n0 + r) * K + k0 + c4 * 4);
        }

        __syncthreads();  // previous compute done before overwriting smem

        // ---- split + store to smem ----
#pragma unroll
        for (int i = 0; i < 4; i++) {
            int idx = tid + 256 * i;
            int r = idx >> 3, c4 = idx & 7;
            float4 v = av[i], h, l;
            h.x = tf32_rna(v.x); l.x = v.x - h.x;
            h.y = tf32_rna(v.y); l.y = v.y - h.y;
            h.z = tf32_rna(v.z); l.z = v.z - h.z;
            h.w = tf32_rna(v.w); l.w = v.w - h.w;
            *(float4*)&As_hi[r * LDS_PAD + c4 * 4] = h;
            *(float4*)&As_lo[r * LDS_PAD + c4 * 4] = l;
        }
#pragma unroll
        for (int i = 0; i < 2; i++) {
            int idx = tid + 256 * i;
            int r = idx >> 3, c4 = idx & 7;
            float4 v = bv[i], h, l;
            h.x = tf32_rna(v.x); l.x = v.x - h.x;
            h.y = tf32_rna(v.y); l.y = v.y - h.y;
            h.z = tf32_rna(v.z); l.z = v.z - h.z;
            h.w = tf32_rna(v.w); l.w = v.w - h.w;
            *(float4*)&Bs_hi[r * LDS_PAD + c4 * 4] = h;
            *(float4*)&Bs_lo[r * LDS_PAD + c4 * 4] = l;
        }
        __syncthreads();

        // ---- 4 k-steps of m16n8k8 ----
#pragma unroll
        for (int kk = 0; kk < 4; kk++) {
            const int kb = kk * 8;
            uint32_t a_hi[2][4], a_lo[2][4];
#pragma unroll
            for (int tm = 0; tm < 2; tm++) {
                int r = wm * 32 + tm * 16 + gid;
                a_hi[tm][0] = __float_as_uint(As_hi[r * LDS_PAD + kb + qid]);
                a_hi[tm][1] = __float_as_uint(As_hi[(r + 8) * LDS_PAD + kb + qid]);
                a_hi[tm][2] = __float_as_uint(As_hi[r * LDS_PAD + kb + qid + 4]);
                a_hi[tm][3] = __float_as_uint(As_hi[(r + 8) * LDS_PAD + kb + qid + 4]);
                a_lo[tm][0] = __float_as_uint(As_lo[r * LDS_PAD + kb + qid]);
                a_lo[tm][1] = __float_as_uint(As_lo[(r + 8) * LDS_PAD + kb + qid]);
                a_lo[tm][2] = __float_as_uint(As_lo[r * LDS_PAD + kb + qid + 4]);
                a_lo[tm][3] = __float_as_uint(As_lo[(r + 8) * LDS_PAD + kb + qid + 4]);
            }
            uint32_t b_hi[4][2], b_lo[4][2];
#pragma unroll
            for (int tn = 0; tn < 4; tn++) {
                int c = wn * 32 + tn * 8 + gid;
                b_hi[tn][0] = __float_as_uint(Bs_hi[c * LDS_PAD + kb + qid]);
                b_hi[tn][1] = __float_as_uint(Bs_hi[c * LDS_PAD + kb + qid + 4]);
                b_lo[tn][0] = __float_as_uint(Bs_lo[c * LDS_PAD + kb + qid]);
                b_lo[tn][1] = __float_as_uint(Bs_lo[c * LDS_PAD + kb + qid + 4]);
            }
#pragma unroll
            for (int tm = 0; tm < 2; tm++)
#pragma unroll
                for (int tn = 0; tn < 4; tn++) {
                    mma_tf32(acc[tm][tn], a_hi[tm], b_hi[tn]);
                    mma_tf32(acc[tm][tn], a_hi[tm], b_lo[tn]);
                    mma_tf32(acc[tm][tn], a_lo[tm], b_hi[tn]);
                }
        }
    }

    // ---- epilogue: bias (+relu), write fp32 ----
#pragma unroll
    for (int tm = 0; tm < 2; tm++) {
#pragma unroll
        for (int tn = 0; tn < 4; tn++) {
            const float* d = acc[tm][tn];
            int row = m0 + wm * 32 + tm * 16 + gid;
            int col = n0 + wn * 32 + tn * 8 + 2 * qid;
            float bx = bias[col], by = bias[col + 1];
            float2 v0 = make_float2(d[0] + bx, d[1] + by);
            float2 v1 = make_float2(d[2] + bx, d[3] + by);
            if (relu) {
                v0.x = fmaxf(v0.x, 0.f); v0.y = fmaxf(v0.y, 0.f);
                v1.x = fmaxf(v1.x, 0.f); v1.y = fmaxf(v1.y, 0.f);
            }
            *(float2*)(C + (size_t)row * N + col) = v0;
            *(float2*)(C + (size_t)(row + 8) * N + col) = v1;
        }
    }
}

// ---------------- flash-style attention (fp32, proven R2 version) ----------
__global__ void attn_kernel(const float* __restrict__ qkv, float* __restrict__ out)
{
    __shared__ float Ks[64][32];
    __shared__ float Vs[64][32];

    const int g  = blockIdx.x >> 3;
    const int h  = blockIdx.x & 7;
    const int tid = threadIdx.x;
    const int qi = blockIdx.y * 128 + tid;       // 0..511
    const int hc = h * HD;
    const float* base = qkv + (size_t)g * NN * (3 * E);

    float q[HD];
#pragma unroll
    for (int d = 0; d < HD; d++) q[d] = base[(size_t)qi * (3 * E) + hc + d];

    float acc[HD];
#pragma unroll
    for (int d = 0; d < HD; d++) acc[d] = 0.f;
    float mval = -1e30f, l = 0.f;
    const float scale = 0.17677669529663687f;    // 1/sqrt(32)

#pragma unroll 1
    for (int kt = 0; kt < NN; kt += 64) {
        const int row  = tid >> 1;
        const int half = (tid & 1) * 16;
        const float* kp = base + (size_t)(kt + row) * (3 * E) + E + hc + half;
        const float* vp = base + (size_t)(kt + row) * (3 * E) + 2 * E + hc + half;
#pragma unroll
        for (int c = 0; c < 16; c += 4) {
            *(float4*)&Ks[row][half + c] = *(const float4*)(kp + c);
            *(float4*)&Vs[row][half + c] = *(const float4*)(vp + c);
        }
        __syncthreads();

#pragma unroll 1
        for (int jc = 0; jc < 64; jc += 16) {
            float s[16];
            float cmax = -1e30f;
#pragma unroll
            for (int j = 0; j < 16; j++) {
                float sv = 0.f;
#pragma unroll
                for (int d = 0; d < HD; d++) sv = fmaf(q[d], Ks[jc + j][d], sv);
                sv *= scale;
                s[j] = sv;
                cmax = fmaxf(cmax, sv);
            }
            float mnew = fmaxf(mval, cmax);
            float corr = __expf(mval - mnew);
            l *= corr;
#pragma unroll
            for (int d = 0; d < HD; d++) acc[d] *= corr;
#pragma unroll
            for (int j = 0; j < 16; j++) {
                float p = __expf(s[j] - mnew);
                l += p;
#pragma unroll
                for (int d = 0; d < HD; d++)
                    acc[d] = fmaf(p, Vs[jc + j][d], acc[d]);
            }
            mval = mnew;
        }
        __syncthreads();
    }

    float inv = 1.f / l;
    float* op = out + (size_t)(g * NN + qi) * E + hc;
#pragma unroll
    for (int d = 0; d < HD; d++) op[d] = acc[d] * inv;
}

// ---------------- fused residual + LayerNorm (two-pass, fp32) --------------
__global__ void ln_kernel(float* __restrict__ h, const float* __restrict__ add,
                          const float* __restrict__ w, const float* __restrict__ b)
{
    __shared__ float red[256];
    const int r = blockIdx.x;
    const int t = threadIdx.x;
    const size_t off = (size_t)r * E + t;
    float x = h[off] + add[off];

    red[t] = x;
    __syncthreads();
#pragma unroll
    for (int s = 128; s > 0; s >>= 1) {
        if (t < s) red[t] += red[t + s];
        __syncthreads();
    }
    float mu = red[0] * (1.f / E);
    __syncthreads();

    float d = x - mu;
    red[t] = d * d;
    __syncthreads();
#pragma unroll
    for (int s = 128; s > 0; s >>= 1) {
        if (t < s) red[t] += red[t + s];
        __syncthreads();
    }
    float var = red[0] * (1.f / E);
    float y = d * rsqrtf(var + 1e-5f) * w[t] + b[t];
    h[off] = y;
}

// ---------------- score + sigmoid (warp per row) ---------------------------
__global__ void score_kernel(const float* __restrict__ h, const float* __restrict__ sw,
                             const float* __restrict__ sb, float* __restrict__ probs)
{
    const int warp = (blockIdx.x * blockDim.x + threadIdx.x) >> 5;
    const int lane = threadIdx.x & 31;
    if (warp >= GN) return;
    const float* hp = h + (size_t)warp * E;
    float s = 0.f;
#pragma unroll
    for (int k = 0; k < 8; k++) s = fmaf(hp[lane + k * 32], sw[lane + k * 32], s);
#pragma unroll
    for (int o = 16; o; o >>= 1) s += __shfl_xor_sync(0xffffffff, s, o);
    if (lane == 0) {
        s += sb[0];
        probs[warp] = 1.f / (1.f + expf(-s));
    }
}

// ---------------- per-graph top-k (k=128 of n=512) -------------------------
__global__ void topk_kernel(const float* __restrict__ probs,
                            float* __restrict__ out, float* __restrict__ pf_buf)
{
    __shared__ unsigned long long keys[NN];
    __shared__ int sidx[KSEL];
    __shared__ int flags[NN];

    const int g = blockIdx.x;
    const int t = threadIdx.x;
    const float p = probs[g * NN + t];

    unsigned int fb = __float_as_uint(p);
    keys[t] = ((unsigned long long)fb << 32) | (unsigned)(NN - 1 - t);
    __syncthreads();

    for (int k = 2; k <= NN; k <<= 1) {
        for (int j = k >> 1; j > 0; j >>= 1) {
            int ixj = t ^ j;
            if (ixj > t) {
                unsigned long long a = keys[t], b = keys[ixj];
                bool up = ((t & k) == 0);
                if (up ? (a < b) : (a > b)) { keys[t] = b; keys[ixj] = a; }
            }
            __syncthreads();
        }
    }

    if (t < KSEL) sidx[t] = NN - 1 - (int)(unsigned)(keys[t] & 0xFFFFFFFFu);
    __syncthreads();

    for (int k = 2; k <= KSEL; k <<= 1) {
        for (int j = k >> 1; j > 0; j >>= 1) {
            int ixj = t ^ j;
            if (t < KSEL && ixj > t && ixj < KSEL) {
                int a = sidx[t], b = sidx[ixj];
                bool up = ((t & k) == 0);
                if (up ? (a > b) : (a < b)) { sidx[t] = b; sidx[ixj] = a; }
            }
            __syncthreads();
        }
    }

    flags[t] = 0;
    __syncthreads();
    if (t < KSEL) flags[sidx[t]] = 1;
    __syncthreads();

    if (t < KSEL)
        out[OFF_SAMP + g * KSEL + t] = (float)(g * NN + sidx[t]);

    float mask = (float)flags[t];
    float ind  = (mask - p) + p;
    float pf   = p * ind;
    pf_buf[g * NN + t] = pf;
    out[OFF_PF + g * NN + t] = pf;
}

// ---------------- edge weights ---------------------------------------------
__global__ void ew_kernel(const int* __restrict__ ei, const float* __restrict__ w,
                          const float* __restrict__ pf, float* __restrict__ out)
{
    int e = blockIdx.x * blockDim.x + threadIdx.x;
    if (e < NE_EDGE) {
        int s = ei[e];
        int d = ei[NE_EDGE + e];
        out[e] = w[e] * pf[s] * pf[d];
    }
}

// ---------------------------------------------------------------------------
extern "C" void kernel_launch(void* const* d_in, const int* in_sizes, int n_in,
                              void* d_out, int out_size)
{
    const float* x      = (const float*)d_in[0];
    const int*   ei     = (const int*)  d_in[1];
    const float* ew     = (const float*)d_in[2];
    const float* emb_w  = (const float*)d_in[3];
    const float* emb_b  = (const float*)d_in[4];
    const float* qkv_w  = (const float*)d_in[5];
    const float* qkv_b  = (const float*)d_in[6];
    const float* out_w  = (const float*)d_in[7];
    const float* out_b  = (const float*)d_in[8];
    const float* ln1_w  = (const float*)d_in[9];
    const float* ln1_b  = (const float*)d_in[10];
    const float* ln2_w  = (const float*)d_in[11];
    const float* ln2_b  = (const float*)d_in[12];
    const float* ff1_w  = (const float*)d_in[13];
    const float* ff1_b  = (const float*)d_in[14];
    const float* ff2_w  = (const float*)d_in[15];
    const float* ff2_b  = (const float*)d_in[16];
    const float* sc_w   = (const float*)d_in[17];
    const float* sc_b   = (const float*)d_in[18];
    float* out = (float*)d_out;

    float *h, *qkvb, *attn, *ff, *probs, *pf;
    cudaGetSymbolAddress((void**)&h,     g_h);
    cudaGetSymbolAddress((void**)&qkvb,  g_qkv);
    cudaGetSymbolAddress((void**)&attn,  g_attn);
    cudaGetSymbolAddress((void**)&ff,    g_ff);
    cudaGetSymbolAddress((void**)&probs, g_probs);
    cudaGetSymbolAddress((void**)&pf,    g_pf);

    cudaFuncSetAttribute(gemm_mma, cudaFuncAttributeMaxDynamicSharedMemorySize, GEMM_SMEM);

    // embedding: [GN,128] @ [256,128]^T -> h [GN,256]
    gemm_mma<<<dim3(E / BN, GN / BM), 256, GEMM_SMEM>>>(x, emb_w, emb_b, h, D_IN, E, 0);

    for (int l = 0; l < NL; l++) {
        const float* qw = qkv_w + (size_t)l * 3 * E * E;
        const float* qb = qkv_b + (size_t)l * 3 * E;
        const float* ow = out_w + (size_t)l * E * E;
        const float* ob = out_b + (size_t)l * E;
        const float* f1w = ff1_w + (size_t)l * DFF * E;
        const float* f1b = ff1_b + (size_t)l * DFF;
        const float* f2w = ff2_w + (size_t)l * E * DFF;
        const float* f2b = ff2_b + (size_t)l * E;

        // qkv projection -> g_qkv [GN, 768]
        gemm_mma<<<dim3(3 * E / BN, GN / BM), 256, GEMM_SMEM>>>(h, qw, qb, qkvb, E, 3 * E, 0);
        // attention -> g_attn [GN, 256]
        attn_kernel<<<dim3(NG * NH, NN / 128), 128>>>(qkvb, attn);
        // output projection -> g_ff (first GN*E floats)
        gemm_mma<<<dim3(E / BN, GN / BM), 256, GEMM_SMEM>>>(attn, ow, ob, ff, E, E, 0);
        // h = LN1(h + proj)
        ln_kernel<<<GN, E>>>(h, ff, ln1_w + (size_t)l * E, ln1_b + (size_t)l * E);
        // ff1 + relu -> g_ff [GN, 2048]
        gemm_mma<<<dim3(DFF / BN, GN / BM), 256, GEMM_SMEM>>>(h, f1w, f1b, ff, E, DFF, 1);
        // ff2 -> g_attn [GN, 256]
        gemm_mma<<<dim3(E / BN, GN / BM), 256, GEMM_SMEM>>>(ff, f2w, f2b, attn, DFF, E, 0);
        // h = LN2(h + ff)
        ln_kernel<<<GN, E>>>(h, attn, ln2_w + (size_t)l * E, ln2_b + (size_t)l * E);
    }

    // score + sigmoid
    score_kernel<<<(GN * 32 + 255) / 256, 256>>>(h, sc_w, sc_b, probs);
    // per-graph top-k, probs_f, sampled_nodes
    topk_kernel<<<NG, NN>>>(probs, out, pf);
    // edge weights
    ew_kernel<<<(NE_EDGE + 255) / 256, 256>>>(ei, ew, pf, out);
}